// round 15
// baseline (speedup 1.0000x reference)
#include <cuda_runtime.h>
#include <cuda_bf16.h>
#include <cstdint>

#define NTOK 16384
#define KEMB 8192
#define CDIM 256

#define LOSS_OFF  4194304
#define PERP_OFF  4194305
#define IDX_OFF   4194306
#define SOFT_OFF  4210690ull

#define NT 128                 // 8192 cols / 64 per tile
#define BPAD 264               // padded bf16 per B row (528 B)
#define BPADB 528
#define LOB (64 * BPADB)       // byte offset of lo block inside a buffer (33792)
#define BUFB (2 * 64 * BPADB)  // bytes per ring buffer (67584)

// ---------------- scratch (static device globals; no allocation) ----------------
__device__ float         g_fn[NTOK * CDIM];       // normalized inputs  [N][C] fp32
__device__ __nv_bfloat16 g_whk[KEMB * CDIM];      // codebook normalized, bf16 hi [K][C]
__device__ __nv_bfloat16 g_wlk[KEMB * CDIM];      // codebook normalized, bf16 lo [K][C]
__device__ float         g_wn[KEMB * CDIM];       // codebook normalized fp32 (refine)
__device__ float g_fn2e[NTOK];
__device__ float g_wn2[KEMB];
__device__ float g_wn2e[KEMB];
__device__ float g_Z[NTOK];
__device__ int   g_idx[NTOK];
__device__ int   g_cand[NTOK][4];
__device__ int   g_counts[KEMB];
__device__ float g_losspart[NTOK];

// ---------------- helpers ----------------
__device__ __forceinline__ uint32_t smem_u32(const void* p) {
    uint32_t a;
    asm("{ .reg .u64 t; cvta.to.shared.u64 t, %1; cvt.u32.u64 %0, t; }" : "=r"(a) : "l"(p));
    return a;
}
__device__ __forceinline__ void cpa16_s(void* dst, const void* src) {
    uint32_t s = smem_u32(dst);
    asm volatile("cp.async.cg.shared.global [%0], [%1], 16;" :: "r"(s), "l"(src));
}
__device__ __forceinline__ void mma_bf16(float* d, const uint32_t* a, const uint32_t* b) {
    asm volatile(
        "mma.sync.aligned.m16n8k16.row.col.f32.bf16.bf16.f32 "
        "{%0,%1,%2,%3}, {%4,%5,%6,%7}, {%8,%9}, {%0,%1,%2,%3};"
        : "+f"(d[0]), "+f"(d[1]), "+f"(d[2]), "+f"(d[3])
        : "r"(a[0]), "r"(a[1]), "r"(a[2]), "r"(a[3]), "r"(b[0]), "r"(b[1]));
}
__device__ __forceinline__ void ldsm_x4(uint32_t* r, uint32_t addr) {
    asm volatile("ldmatrix.sync.aligned.m8n8.x4.shared.b16 {%0,%1,%2,%3}, [%4];"
        : "=r"(r[0]), "=r"(r[1]), "=r"(r[2]), "=r"(r[3]) : "r"(addr));
}
__device__ __forceinline__ void packhl(float x0, float x1, uint32_t& h, uint32_t& l) {
    __nv_bfloat16 h0 = __float2bfloat16(x0), h1 = __float2bfloat16(x1);
    h = ((uint32_t)__bfloat16_as_ushort(h1) << 16) | __bfloat16_as_ushort(h0);
    float l0 = x0 - __bfloat162float(h0), l1 = x1 - __bfloat162float(h1);
    __nv_bfloat16 b0 = __float2bfloat16(l0), b1 = __float2bfloat16(l1);
    l = ((uint32_t)__bfloat16_as_ushort(b1) << 16) | __bfloat16_as_ushort(b0);
}

// ---------------- prep: normalize codebook -> bf16 hi/lo [K][C] + fp32 ----------------
__global__ void prep_w(const float* __restrict__ emb) {
    int warp = threadIdx.x >> 5, lane = threadIdx.x & 31;
    int k = blockIdx.x * 8 + warp;
    float v[8];
#pragma unroll
    for (int j = 0; j < 8; j++) v[j] = emb[(size_t)k * CDIM + lane + 32 * j];
    float s = 0.f;
#pragma unroll
    for (int j = 0; j < 8; j++) s = fmaf(v[j], v[j], s);
#pragma unroll
    for (int o = 16; o; o >>= 1) s += __shfl_xor_sync(0xffffffffu, s, o);
    float den = fmaxf(sqrtf(s), 1e-12f);
    float t2 = 0.f;
#pragma unroll
    for (int j = 0; j < 8; j++) {
        float wn = v[j] / den;
        int c = lane + 32 * j;
        g_wn[(size_t)k * CDIM + c] = wn;
        __nv_bfloat16 h = __float2bfloat16(wn);
        g_whk[(size_t)k * CDIM + c] = h;
        g_wlk[(size_t)k * CDIM + c] = __float2bfloat16(wn - __bfloat162float(h));
        t2 = fmaf(wn, wn, t2);
    }
#pragma unroll
    for (int o = 16; o; o >>= 1) t2 += __shfl_xor_sync(0xffffffffu, t2, o);
    if (lane == 0) { g_wn2[k] = t2; g_wn2e[k] = t2 * 1.44269504f; }
}

// ---------------- prep: normalize inputs (NHWC gather) ----------------
__global__ void prep_x(const float* __restrict__ in) {
    int warp = threadIdx.x >> 5, lane = threadIdx.x & 31;
    int n = blockIdx.x * 8 + warp;
    int b = n >> 10, h = (n >> 5) & 31, w = n & 31;
    const float* base = in + (size_t)b * 262144 + h * 32 + w;
    float v[8];
#pragma unroll
    for (int j = 0; j < 8; j++) v[j] = base[(size_t)(lane + 32 * j) * 1024];
    float s = 0.f;
#pragma unroll
    for (int j = 0; j < 8; j++) s = fmaf(v[j], v[j], s);
#pragma unroll
    for (int o = 16; o; o >>= 1) s += __shfl_xor_sync(0xffffffffu, s, o);
    float den = fmaxf(sqrtf(s), 1e-12f);
    float t2 = 0.f;
#pragma unroll
    for (int j = 0; j < 8; j++) {
        float fn = v[j] / den;
        g_fn[(size_t)n * CDIM + lane + 32 * j] = fn;
        t2 = fmaf(fn, fn, t2);
    }
#pragma unroll
    for (int o = 16; o; o >>= 1) t2 += __shfl_xor_sync(0xffffffffu, t2, o);
    if (lane == 0) g_fn2e[n] = t2 * 1.44269504f;
}

__global__ void zero_counts() {
    int t = blockIdx.x * 256 + threadIdx.x;
    if (t < KEMB) g_counts[t] = 0;
}

// ---------------- B tile fill: 64 codewords x 256 dims, hi+lo, padded rows -------------
__device__ __forceinline__ void load_btile(char* ring, int buf, int tile, int tid) {
    char* base = ring + (size_t)buf * BUFB;
#pragma unroll
    for (int j = 0; j < 16; j++) {
        int q = tid + 256 * j;          // 0..4095 16B chunks
        int isLo = q >> 11;
        int qq = q & 2047;
        int r = qq >> 5;                // codeword row 0..63
        int c = qq & 31;                // 16B chunk in row (8 bf16)
        char* dst = base + isLo * LOB + r * BPADB + c * 16;
        const __nv_bfloat16* src = (isLo ? g_wlk : g_whk) + (size_t)(tile * 64 + r) * CDIM + c * 8;
        cpa16_s(dst, src);
    }
}

// ---------------- main: HMMA (mma.sync bf16 hi/lo) + fused exp / top-2 / rowsum --------
// CTA: 128 tokens, 8 warps; warp owns 16 rows. A fragments in registers (hi+lo).
// B: 3-deep cp.async ring of 64-col tiles; fragments via ldmatrix.x4.
__global__ __launch_bounds__(256, 1) void vq_mma(float* __restrict__ out) {
    extern __shared__ __align__(16) char dsm[];

    const int tid = threadIdx.x;
    const int wid = tid >> 5, lane = tid & 31;
    const int g = lane >> 2, q = lane & 3;
    const int row0 = blockIdx.x * 128;
    const int rowA = row0 + wid * 16 + g;        // this thread's first row; second = +8
    const uint32_t sb = smem_u32(dsm);
    // per-lane ldmatrix row offset: lanes 0-7 hi@k, 8-15 hi@k+8, 16-23 lo@k, 24-31 lo@k+8
    const uint32_t rb = (uint32_t)(lane & 7) * BPADB + ((lane >> 4) & 1) * LOB + ((lane >> 3) & 1) * 16;

    // ---- A fragments: load fp32, split to bf16 hi/lo, keep in registers ----
    uint32_t ahi[16][4], alo[16][4];
    {
        const float* fr0 = g_fn + (size_t)rowA * CDIM;
        const float* fr1 = fr0 + 8 * CDIM;
#pragma unroll
        for (int k = 0; k < 16; k++) {
            int c0 = k * 16 + q * 2;
            float2 x00 = *(const float2*)(fr0 + c0);
            float2 x10 = *(const float2*)(fr1 + c0);
            float2 x01 = *(const float2*)(fr0 + c0 + 8);
            float2 x11 = *(const float2*)(fr1 + c0 + 8);
            packhl(x00.x, x00.y, ahi[k][0], alo[k][0]);
            packhl(x10.x, x10.y, ahi[k][1], alo[k][1]);
            packhl(x01.x, x01.y, ahi[k][2], alo[k][2]);
            packhl(x11.x, x11.y, ahi[k][3], alo[k][3]);
        }
    }
    const float a2e0 = g_fn2e[rowA];
    const float a2e1 = g_fn2e[rowA + 8];

    float rsum[2] = {0.f, 0.f};
    float rm1[2] = {3.4e38f, 3.4e38f}, rm2[2] = {3.4e38f, 3.4e38f};
    int ri1[2] = {0x7fffffff, 0x7fffffff}, ri2[2] = {0x7fffffff, 0x7fffffff};

    float* soft = out + SOFT_OFF;

    // prologue: tiles 0,1 in flight
    load_btile(dsm, 0, 0, tid); asm volatile("cp.async.commit_group;");
    load_btile(dsm, 1, 1, tid); asm volatile("cp.async.commit_group;");

    for (int t = 0; t < NT; ++t) {
        if (t + 2 < NT) {
            load_btile(dsm, (t + 2) % 3, t + 2, tid);
            asm volatile("cp.async.commit_group;");
            asm volatile("cp.async.wait_group 2;");
        } else if (t + 1 < NT) {
            asm volatile("cp.async.wait_group 1;");
        } else {
            asm volatile("cp.async.wait_group 0;");
        }
        __syncthreads();                       // B[t] visible

        const uint32_t tb = sb + (uint32_t)(t % 3) * BUFB + rb;
        float acc[8][4];
#pragma unroll
        for (int n = 0; n < 8; n++)
#pragma unroll
            for (int j = 0; j < 4; j++) acc[n][j] = 0.f;

#pragma unroll
        for (int k = 0; k < 16; k++) {
#pragma unroll
            for (int ng = 0; ng < 2; ng++) {
                uint32_t f[4][4];
#pragma unroll
                for (int j = 0; j < 4; j++)
                    ldsm_x4(f[j], tb + (uint32_t)(ng * 4 + j) * (8 * BPADB) + (uint32_t)k * 32);
                // interleave segments across 4 accs for ILP
#pragma unroll
                for (int j = 0; j < 4; j++) mma_bf16(acc[ng * 4 + j], ahi[k], &f[j][0]);
#pragma unroll
                for (int j = 0; j < 4; j++) mma_bf16(acc[ng * 4 + j], alo[k], &f[j][0]);
#pragma unroll
                for (int j = 0; j < 4; j++) mma_bf16(acc[ng * 4 + j], ahi[k], &f[j][2]);
            }
        }

        // fused epilogue for tile t (cols t*64 .. +63)
        const int cb = t * 64;
#pragma unroll
        for (int n = 0; n < 8; n++) {
            int c0 = cb + n * 8 + q * 2;
            float w2a = g_wn2[c0], w2b = g_wn2[c0 + 1];
            float wea = g_wn2e[c0], web = g_wn2e[c0 + 1];
#pragma unroll
            for (int s = 0; s < 2; s++) {
                float d0 = acc[n][s * 2 + 0], d1 = acc[n][s * 2 + 1];
                float a2 = s ? a2e1 : a2e0;
                float m0 = fmaf(d0, -2.0f, w2a);
                float m1v = fmaf(d1, -2.0f, w2b);
                if (m0 < rm2[s]) {
                    if (m0 < rm1[s]) { rm2[s] = rm1[s]; ri2[s] = ri1[s]; rm1[s] = m0; ri1[s] = c0; }
                    else             { rm2[s] = m0; ri2[s] = c0; }
                }
                if (m1v < rm2[s]) {
                    if (m1v < rm1[s]) { rm2[s] = rm1[s]; ri2[s] = ri1[s]; rm1[s] = m1v; ri1[s] = c0 + 1; }
                    else              { rm2[s] = m1v; ri2[s] = c0 + 1; }
                }
                float t0 = fmaf(d0, 2.88539008f, -(a2 + wea));
                float t1 = fmaf(d1, 2.88539008f, -(a2 + web));
                float e0, e1;
                asm("ex2.approx.f32 %0, %1;" : "=f"(e0) : "f"(t0));
                asm("ex2.approx.f32 %0, %1;" : "=f"(e1) : "f"(t1));
                rsum[s] += e0 + e1;
                *(float2*)(soft + (size_t)(rowA + s * 8) * KEMB + c0) = make_float2(e0, e1);
            }
        }
        __syncthreads();                       // all reads of B[t] done before ring reuse
    }

    // ---- CTA reduction: rowsum Z + top-4 candidates (deterministic) ----
    float* rs = (float*)dsm;                   // [128][4]
    float* m1a = rs + 512;                     // [128][4]
    float* m2a = m1a + 512;
    int*   i1a = (int*)(m2a + 512);
    int*   i2a = i1a + 512;
    __syncthreads();
#pragma unroll
    for (int s = 0; s < 2; s++) {
        int rl = wid * 16 + g + s * 8;
        rs[rl * 4 + q]  = rsum[s];
        m1a[rl * 4 + q] = rm1[s];
        m2a[rl * 4 + q] = rm2[s];
        i1a[rl * 4 + q] = ri1[s];
        i2a[rl * 4 + q] = ri2[s];
    }
    __syncthreads();
    if (tid < 128) {
        int r = tid;
        float sum = rs[r * 4] + rs[r * 4 + 1] + rs[r * 4 + 2] + rs[r * 4 + 3];
        g_Z[row0 + r] = sum;
        float bm[4]; int bi[4];
#pragma unroll
        for (int j = 0; j < 4; j++) { bm[j] = 3.4e38f; bi[j] = 0x7fffffff; }
        for (int u = 0; u < 8; u++) {
            float m = (u & 1) ? m2a[r * 4 + (u >> 1)] : m1a[r * 4 + (u >> 1)];
            int  iv = (u & 1) ? i2a[r * 4 + (u >> 1)] : i1a[r * 4 + (u >> 1)];
            if (m < bm[3] || (m == bm[3] && iv < bi[3])) {
                int j = 3;
                while (j > 0 && (m < bm[j - 1] || (m == bm[j - 1] && iv < bi[j - 1]))) {
                    bm[j] = bm[j - 1]; bi[j] = bi[j - 1]; --j;
                }
                bm[j] = m; bi[j] = iv;
            }
        }
#pragma unroll
        for (int j = 0; j < 4; j++) g_cand[row0 + r][j] = bi[j];
    }
}

// ---------------- argmin refine: exact (double) over 4 candidates ----------------
__global__ void refine_k() {
    int warp = threadIdx.x >> 5, lane = threadIdx.x & 31;
    int n = blockIdx.x * 8 + warp;
    int cand = lane >> 3, part = lane & 7;
    int k = g_cand[n][cand];
    const float* fnr = g_fn + (size_t)n * CDIM;
    const float* wr  = g_wn + (size_t)k * CDIM;
    double dot = 0.0, w2 = 0.0;
    int c0 = part * 32;
#pragma unroll 8
    for (int c = c0; c < c0 + 32; c++) {
        double w = (double)wr[c];
        dot = fma((double)fnr[c], w, dot);
        w2  = fma(w, w, w2);
    }
#pragma unroll
    for (int o = 1; o < 8; o <<= 1) {
        dot += __shfl_xor_sync(0xffffffffu, dot, o);
        w2  += __shfl_xor_sync(0xffffffffu, w2,  o);
    }
    double d = w2 - 2.0 * dot;
#pragma unroll
    for (int o = 8; o < 32; o <<= 1) {
        double od = __shfl_xor_sync(0xffffffffu, d, o);
        int    ok = __shfl_xor_sync(0xffffffffu, k, o);
        if (od < d || (od == d && ok < k)) { d = od; k = ok; }
    }
    if (lane == 0) g_idx[n] = k;
}

// ---------------- scale soft codes by 1/Z ----------------
__global__ void scale_soft(float* __restrict__ out) {
    float2* soft = (float2*)(out + SOFT_OFF);
    size_t base = (size_t)blockIdx.x * 256 + threadIdx.x;
#pragma unroll
    for (int qq = 0; qq < 4; qq++) {
        size_t i = base + (size_t)qq * 16777216u;
        int n = (int)(i >> 12);
        float inv = 1.0f / g_Z[n];
        float2 v = soft[i];
        v.x *= inv; v.y *= inv;
        soft[i] = v;
    }
}

// ---------------- gather quantized, loss partials, counts, indices ----------------
__global__ void quantize_k(const float* __restrict__ in, const float* __restrict__ emb,
                           float* __restrict__ out) {
    int warp = threadIdx.x >> 5, lane = threadIdx.x & 31;
    int n = blockIdx.x * 8 + warp;
    int idx = g_idx[n];
    int b = n >> 10, h = (n >> 5) & 31, w = n & 31;
    const float* er = emb + (size_t)idx * CDIM;
    const float* xb = in + (size_t)b * 262144 + h * 32 + w;
    float* ob = out + (size_t)b * 262144 + w * 32 + h;   // [B,C,W,H]
    float ls = 0.f;
#pragma unroll
    for (int j = 0; j < 8; j++) {
        int c = lane + 32 * j;
        float qv = er[c];
        float x = xb[(size_t)c * 1024];
        float d = qv - x;
        ls = fmaf(d, d, ls);
        ob[(size_t)c * 1024] = qv;
    }
#pragma unroll
    for (int o = 16; o; o >>= 1) ls += __shfl_xor_sync(0xffffffffu, ls, o);
    if (lane == 0) {
        g_losspart[n] = ls;
        atomicAdd(&g_counts[idx], 1);
        out[IDX_OFF + n] = (float)idx;
    }
}

// ---------------- final scalars ----------------
__global__ void finalize_k(float* __restrict__ out) {
    __shared__ float sred[1024];
    int tid = threadIdx.x;
    float s = 0.f;
    for (int i = 0; i < 16; i++) s += g_losspart[tid + 1024 * i];
    sred[tid] = s; __syncthreads();
    for (int o = 512; o; o >>= 1) { if (tid < o) sred[tid] += sred[tid + o]; __syncthreads(); }
    if (tid == 0) out[LOSS_OFF] = 0.25f * (sred[0] * (1.0f / 4194304.0f));
    __syncthreads();
    float e = 0.f;
    for (int i = 0; i < 8; i++) {
        float p = (float)g_counts[tid + 1024 * i] * (1.0f / 16384.0f);
        e += p * logf(p + 1e-10f);
    }
    sred[tid] = e; __syncthreads();
    for (int o = 512; o; o >>= 1) { if (tid < o) sred[tid] += sred[tid + o]; __syncthreads(); }
    if (tid == 0) out[PERP_OFF] = expf(-sred[0]);
}

// ---------------- launcher ----------------
extern "C" void kernel_launch(void* const* d_in, const int* in_sizes, int n_in,
                              void* d_out, int out_size) {
    (void)in_sizes; (void)n_in; (void)out_size;
    const float* in  = (const float*)d_in[0];
    const float* emb = (const float*)d_in[1];
    float* out = (float*)d_out;

    const int dyn = 3 * BUFB;            // 202752 bytes
    cudaFuncSetAttribute(vq_mma, cudaFuncAttributeMaxDynamicSharedMemorySize, dyn);

    prep_w<<<KEMB / 8, 256>>>(emb);
    prep_x<<<NTOK / 8, 256>>>(in);
    zero_counts<<<32, 256>>>();
    vq_mma<<<NTOK / 128, 256, dyn>>>(out);
    refine_k<<<NTOK / 8, 256>>>();
    scale_soft<<<65536, 256>>>(out);
    quantize_k<<<NTOK / 8, 256>>>(in, emb, out);
    finalize_k<<<1, 1024>>>(out);
}

// round 16
// speedup vs baseline: 1.1272x; 1.1272x over previous
#include <cuda_runtime.h>
#include <cuda_bf16.h>
#include <cstdint>

#define NTOK 16384
#define KEMB 8192
#define CDIM 256

#define LOSS_OFF  4194304
#define PERP_OFF  4194305
#define IDX_OFF   4194306
#define SOFT_OFF  4210690ull

#define NT 256                 // 8192 cols / 32 per tile
#define BPAD 264               // padded bf16 per B row
#define BPADB 528              // bytes per B row
#define LOB (32 * BPADB)       // byte offset of lo block inside a buffer (16896)
#define BUFB (2 * 32 * BPADB)  // bytes per ring buffer (33792)

// ---------------- scratch (static device globals; no allocation) ----------------
__device__ float         g_fn[NTOK * CDIM];       // normalized inputs  [N][C] fp32
__device__ __nv_bfloat16 g_whk[KEMB * CDIM];      // codebook normalized, bf16 hi [K][C]
__device__ __nv_bfloat16 g_wlk[KEMB * CDIM];      // codebook normalized, bf16 lo [K][C]
__device__ float         g_wn[KEMB * CDIM];       // codebook normalized fp32 (refine)
__device__ float g_fn2e[NTOK];
__device__ float g_wn2[KEMB];
__device__ float g_wn2e[KEMB];
__device__ float g_Z[NTOK];
__device__ int   g_idx[NTOK];
__device__ int   g_cand[NTOK][4];
__device__ int   g_counts[KEMB];
__device__ float g_losspart[NTOK];

// ---------------- helpers ----------------
__device__ __forceinline__ uint32_t smem_u32(const void* p) {
    uint32_t a;
    asm("{ .reg .u64 t; cvta.to.shared.u64 t, %1; cvt.u32.u64 %0, t; }" : "=r"(a) : "l"(p));
    return a;
}
__device__ __forceinline__ void cpa16_s(void* dst, const void* src) {
    uint32_t s = smem_u32(dst);
    asm volatile("cp.async.cg.shared.global [%0], [%1], 16;" :: "r"(s), "l"(src));
}
__device__ __forceinline__ void mma_bf16(float* d, const uint32_t* a, const uint32_t* b) {
    asm volatile(
        "mma.sync.aligned.m16n8k16.row.col.f32.bf16.bf16.f32 "
        "{%0,%1,%2,%3}, {%4,%5,%6,%7}, {%8,%9}, {%0,%1,%2,%3};"
        : "+f"(d[0]), "+f"(d[1]), "+f"(d[2]), "+f"(d[3])
        : "r"(a[0]), "r"(a[1]), "r"(a[2]), "r"(a[3]), "r"(b[0]), "r"(b[1]));
}
__device__ __forceinline__ void ldsm_x4(uint32_t* r, uint32_t addr) {
    asm volatile("ldmatrix.sync.aligned.m8n8.x4.shared.b16 {%0,%1,%2,%3}, [%4];"
        : "=r"(r[0]), "=r"(r[1]), "=r"(r[2]), "=r"(r[3]) : "r"(addr));
}
__device__ __forceinline__ void packhl(float x0, float x1, uint32_t& h, uint32_t& l) {
    __nv_bfloat16 h0 = __float2bfloat16(x0), h1 = __float2bfloat16(x1);
    h = ((uint32_t)__bfloat16_as_ushort(h1) << 16) | __bfloat16_as_ushort(h0);
    float l0 = x0 - __bfloat162float(h0), l1 = x1 - __bfloat162float(h1);
    __nv_bfloat16 b0 = __float2bfloat16(l0), b1 = __float2bfloat16(l1);
    l = ((uint32_t)__bfloat16_as_ushort(b1) << 16) | __bfloat16_as_ushort(b0);
}

// ---------------- prep: normalize codebook -> bf16 hi/lo [K][C] + fp32 ----------------
__global__ void prep_w(const float* __restrict__ emb) {
    int warp = threadIdx.x >> 5, lane = threadIdx.x & 31;
    int k = blockIdx.x * 8 + warp;
    float v[8];
#pragma unroll
    for (int j = 0; j < 8; j++) v[j] = emb[(size_t)k * CDIM + lane + 32 * j];
    float s = 0.f;
#pragma unroll
    for (int j = 0; j < 8; j++) s = fmaf(v[j], v[j], s);
#pragma unroll
    for (int o = 16; o; o >>= 1) s += __shfl_xor_sync(0xffffffffu, s, o);
    float den = fmaxf(sqrtf(s), 1e-12f);
    float t2 = 0.f;
#pragma unroll
    for (int j = 0; j < 8; j++) {
        float wn = v[j] / den;
        int c = lane + 32 * j;
        g_wn[(size_t)k * CDIM + c] = wn;
        __nv_bfloat16 h = __float2bfloat16(wn);
        g_whk[(size_t)k * CDIM + c] = h;
        g_wlk[(size_t)k * CDIM + c] = __float2bfloat16(wn - __bfloat162float(h));
        t2 = fmaf(wn, wn, t2);
    }
#pragma unroll
    for (int o = 16; o; o >>= 1) t2 += __shfl_xor_sync(0xffffffffu, t2, o);
    if (lane == 0) { g_wn2[k] = t2; g_wn2e[k] = t2 * 1.44269504f; }
}

// ---------------- prep: normalize inputs (NHWC gather) ----------------
__global__ void prep_x(const float* __restrict__ in) {
    int warp = threadIdx.x >> 5, lane = threadIdx.x & 31;
    int n = blockIdx.x * 8 + warp;
    int b = n >> 10, h = (n >> 5) & 31, w = n & 31;
    const float* base = in + (size_t)b * 262144 + h * 32 + w;
    float v[8];
#pragma unroll
    for (int j = 0; j < 8; j++) v[j] = base[(size_t)(lane + 32 * j) * 1024];
    float s = 0.f;
#pragma unroll
    for (int j = 0; j < 8; j++) s = fmaf(v[j], v[j], s);
#pragma unroll
    for (int o = 16; o; o >>= 1) s += __shfl_xor_sync(0xffffffffu, s, o);
    float den = fmaxf(sqrtf(s), 1e-12f);
    float t2 = 0.f;
#pragma unroll
    for (int j = 0; j < 8; j++) {
        float fn = v[j] / den;
        g_fn[(size_t)n * CDIM + lane + 32 * j] = fn;
        t2 = fmaf(fn, fn, t2);
    }
#pragma unroll
    for (int o = 16; o; o >>= 1) t2 += __shfl_xor_sync(0xffffffffu, t2, o);
    if (lane == 0) g_fn2e[n] = t2 * 1.44269504f;
}

__global__ void zero_counts() {
    int t = blockIdx.x * 256 + threadIdx.x;
    if (t < KEMB) g_counts[t] = 0;
}

// ---------------- B tile fill: 32 codewords x 256 dims, hi+lo, padded rows -------------
__device__ __forceinline__ void load_btile(char* ring, int buf, int tile, int tid) {
    char* base = ring + (size_t)buf * BUFB;
#pragma unroll
    for (int j = 0; j < 8; j++) {
        int q = tid + 256 * j;          // 0..2047 16B chunks
        int isLo = q >> 10;
        int qq = q & 1023;
        int r = qq >> 5;                // codeword row 0..31
        int c = qq & 31;                // 16B chunk in row (8 bf16)
        char* dst = base + isLo * LOB + r * BPADB + c * 16;
        const __nv_bfloat16* src = (isLo ? g_wlk : g_whk) + (size_t)(tile * 32 + r) * CDIM + c * 8;
        cpa16_s(dst, src);
    }
}

// ---------------- main: HMMA (mma.sync bf16 hi/lo) + fused exp / top-2 / rowsum --------
// CTA: 128 tokens, 8 warps; warp owns 16 rows. A fragments in registers (hi+lo).
// B: 4-deep cp.async ring of 32-col tiles; B fragments via ldmatrix.x4.
// MMA order is segment-major (distance-4 acc dependencies) for tensor-pipe ILP.
__global__ __launch_bounds__(256, 1) void vq_mma(float* __restrict__ out) {
    extern __shared__ __align__(16) char dsm[];

    const int tid = threadIdx.x;
    const int wid = tid >> 5, lane = tid & 31;
    const int g = lane >> 2, q = lane & 3;
    const int row0 = blockIdx.x * 128;
    const int rowA = row0 + wid * 16 + g;        // this thread's first row; second = +8
    const uint32_t sb = smem_u32(dsm);
    // ldmatrix lane->address: lanes 0-7 hi@k, 8-15 hi@k+8, 16-23 lo@k, 24-31 lo@k+8
    const uint32_t rb = (uint32_t)(lane & 7) * BPADB
                      + ((lane >> 4) & 1) * LOB
                      + ((lane >> 3) & 1) * 16;

    // ---- A fragments: load fp32, split to bf16 hi/lo, keep in registers ----
    uint32_t ahi[16][4], alo[16][4];
    {
        const float* fr0 = g_fn + (size_t)rowA * CDIM;
        const float* fr1 = fr0 + 8 * CDIM;
#pragma unroll
        for (int k = 0; k < 16; k++) {
            int c0 = k * 16 + q * 2;
            float2 x00 = *(const float2*)(fr0 + c0);
            float2 x10 = *(const float2*)(fr1 + c0);
            float2 x01 = *(const float2*)(fr0 + c0 + 8);
            float2 x11 = *(const float2*)(fr1 + c0 + 8);
            packhl(x00.x, x00.y, ahi[k][0], alo[k][0]);
            packhl(x10.x, x10.y, ahi[k][1], alo[k][1]);
            packhl(x01.x, x01.y, ahi[k][2], alo[k][2]);
            packhl(x11.x, x11.y, ahi[k][3], alo[k][3]);
        }
    }
    const float a2e0 = g_fn2e[rowA];
    const float a2e1 = g_fn2e[rowA + 8];

    float rsum[2] = {0.f, 0.f};
    float rm1[2] = {3.4e38f, 3.4e38f}, rm2[2] = {3.4e38f, 3.4e38f};
    int ri1[2] = {0x7fffffff, 0x7fffffff}, ri2[2] = {0x7fffffff, 0x7fffffff};

    float* soft = out + SOFT_OFF;

    // prologue: tiles 0..2 in flight
    load_btile(dsm, 0, 0, tid); asm volatile("cp.async.commit_group;");
    load_btile(dsm, 1, 1, tid); asm volatile("cp.async.commit_group;");
    load_btile(dsm, 2, 2, tid); asm volatile("cp.async.commit_group;");

    for (int t = 0; t < NT; ++t) {
        if (t + 3 < NT) {
            load_btile(dsm, (t + 3) & 3, t + 3, tid);
            asm volatile("cp.async.commit_group;");
            asm volatile("cp.async.wait_group 3;");
        } else {
            int r = NT - 1 - t;
            if (r == 2)      asm volatile("cp.async.wait_group 2;");
            else if (r == 1) asm volatile("cp.async.wait_group 1;");
            else             asm volatile("cp.async.wait_group 0;");
        }
        __syncthreads();                       // B[t] visible

        const uint32_t tb = sb + (uint32_t)(t & 3) * BUFB + rb;
        float acc[4][4];
#pragma unroll
        for (int n = 0; n < 4; n++)
#pragma unroll
            for (int j = 0; j < 4; j++) acc[n][j] = 0.f;

#pragma unroll
        for (int k = 0; k < 16; k++) {
            // B fragments for all 4 n-groups: f[n] = {bhi0, bhi1, blo0, blo1}
            uint32_t f[4][4];
#pragma unroll
            for (int n = 0; n < 4; n++)
                ldsm_x4(f[n], tb + (uint32_t)n * (8 * BPADB) + (uint32_t)k * 32);
            // segment-major: same-acc dependency distance = 4
#pragma unroll
            for (int n = 0; n < 4; n++) mma_bf16(acc[n], ahi[k], &f[n][0]);
#pragma unroll
            for (int n = 0; n < 4; n++) mma_bf16(acc[n], alo[k], &f[n][0]);
#pragma unroll
            for (int n = 0; n < 4; n++) mma_bf16(acc[n], ahi[k], &f[n][2]);
        }

        // fused epilogue for tile t (cols t*32 .. +31)
        const int cb = t * 32;
#pragma unroll
        for (int n = 0; n < 4; n++) {
            int c0 = cb + n * 8 + q * 2;
            float w2a = g_wn2[c0], w2b = g_wn2[c0 + 1];
            float wea = g_wn2e[c0], web = g_wn2e[c0 + 1];
            // row rowA (acc c0,c1)  /  row rowA+8 (acc c2,c3)
#pragma unroll
            for (int s = 0; s < 2; s++) {
                float d0 = acc[n][s * 2 + 0], d1 = acc[n][s * 2 + 1];
                float a2 = s ? a2e1 : a2e0;
                float m0 = fmaf(d0, -2.0f, w2a);
                float m1v = fmaf(d1, -2.0f, w2b);
                if (m0 < rm2[s]) {
                    if (m0 < rm1[s]) { rm2[s] = rm1[s]; ri2[s] = ri1[s]; rm1[s] = m0; ri1[s] = c0; }
                    else             { rm2[s] = m0; ri2[s] = c0; }
                }
                if (m1v < rm2[s]) {
                    if (m1v < rm1[s]) { rm2[s] = rm1[s]; ri2[s] = ri1[s]; rm1[s] = m1v; ri1[s] = c0 + 1; }
                    else              { rm2[s] = m1v; ri2[s] = c0 + 1; }
                }
                float t0 = fmaf(d0, 2.88539008f, -(a2 + wea));
                float t1 = fmaf(d1, 2.88539008f, -(a2 + web));
                float e0, e1;
                asm("ex2.approx.f32 %0, %1;" : "=f"(e0) : "f"(t0));
                asm("ex2.approx.f32 %0, %1;" : "=f"(e1) : "f"(t1));
                rsum[s] += e0 + e1;
                *(float2*)(soft + (size_t)(rowA + s * 8) * KEMB + c0) = make_float2(e0, e1);
            }
        }
        __syncthreads();                       // all reads of B[t] done before ring reuse
    }

    // ---- CTA reduction: rowsum Z + top-4 candidates (deterministic) ----
    float* rs = (float*)dsm;                   // [128][4]
    float* m1a = rs + 512;                     // [128][4]
    float* m2a = m1a + 512;
    int*   i1a = (int*)(m2a + 512);
    int*   i2a = i1a + 512;
    __syncthreads();
#pragma unroll
    for (int s = 0; s < 2; s++) {
        int rl = wid * 16 + g + s * 8;
        rs[rl * 4 + q]  = rsum[s];
        m1a[rl * 4 + q] = rm1[s];
        m2a[rl * 4 + q] = rm2[s];
        i1a[rl * 4 + q] = ri1[s];
        i2a[rl * 4 + q] = ri2[s];
    }
    __syncthreads();
    if (tid < 128) {
        int r = tid;
        float sum = rs[r * 4] + rs[r * 4 + 1] + rs[r * 4 + 2] + rs[r * 4 + 3];
        g_Z[row0 + r] = sum;
        float bm[4]; int bi[4];
#pragma unroll
        for (int j = 0; j < 4; j++) { bm[j] = 3.4e38f; bi[j] = 0x7fffffff; }
        for (int u = 0; u < 8; u++) {
            float m = (u & 1) ? m2a[r * 4 + (u >> 1)] : m1a[r * 4 + (u >> 1)];
            int  iv = (u & 1) ? i2a[r * 4 + (u >> 1)] : i1a[r * 4 + (u >> 1)];
            if (m < bm[3] || (m == bm[3] && iv < bi[3])) {
                int j = 3;
                while (j > 0 && (m < bm[j - 1] || (m == bm[j - 1] && iv < bi[j - 1]))) {
                    bm[j] = bm[j - 1]; bi[j] = bi[j - 1]; --j;
                }
                bm[j] = m; bi[j] = iv;
            }
        }
#pragma unroll
        for (int j = 0; j < 4; j++) g_cand[row0 + r][j] = bi[j];
    }
}

// ---------------- argmin refine: exact (double) over 4 candidates ----------------
__global__ void refine_k() {
    int warp = threadIdx.x >> 5, lane = threadIdx.x & 31;
    int n = blockIdx.x * 8 + warp;
    int cand = lane >> 3, part = lane & 7;
    int k = g_cand[n][cand];
    const float* fnr = g_fn + (size_t)n * CDIM;
    const float* wr  = g_wn + (size_t)k * CDIM;
    double dot = 0.0, w2 = 0.0;
    int c0 = part * 32;
#pragma unroll 8
    for (int c = c0; c < c0 + 32; c++) {
        double w = (double)wr[c];
        dot = fma((double)fnr[c], w, dot);
        w2  = fma(w, w, w2);
    }
#pragma unroll
    for (int o = 1; o < 8; o <<= 1) {
        dot += __shfl_xor_sync(0xffffffffu, dot, o);
        w2  += __shfl_xor_sync(0xffffffffu, w2,  o);
    }
    double d = w2 - 2.0 * dot;
#pragma unroll
    for (int o = 8; o < 32; o <<= 1) {
        double od = __shfl_xor_sync(0xffffffffu, d, o);
        int    ok = __shfl_xor_sync(0xffffffffu, k, o);
        if (od < d || (od == d && ok < k)) { d = od; k = ok; }
    }
    if (lane == 0) g_idx[n] = k;
}

// ---------------- scale soft codes by 1/Z ----------------
__global__ void scale_soft(float* __restrict__ out) {
    float2* soft = (float2*)(out + SOFT_OFF);
    size_t base = (size_t)blockIdx.x * 256 + threadIdx.x;
#pragma unroll
    for (int qq = 0; qq < 4; qq++) {
        size_t i = base + (size_t)qq * 16777216u;
        int n = (int)(i >> 12);
        float inv = 1.0f / g_Z[n];
        float2 v = soft[i];
        v.x *= inv; v.y *= inv;
        soft[i] = v;
    }
}

// ---------------- gather quantized, loss partials, counts, indices ----------------
__global__ void quantize_k(const float* __restrict__ in, const float* __restrict__ emb,
                           float* __restrict__ out) {
    int warp = threadIdx.x >> 5, lane = threadIdx.x & 31;
    int n = blockIdx.x * 8 + warp;
    int idx = g_idx[n];
    int b = n >> 10, h = (n >> 5) & 31, w = n & 31;
    const float* er = emb + (size_t)idx * CDIM;
    const float* xb = in + (size_t)b * 262144 + h * 32 + w;
    float* ob = out + (size_t)b * 262144 + w * 32 + h;   // [B,C,W,H]
    float ls = 0.f;
#pragma unroll
    for (int j = 0; j < 8; j++) {
        int c = lane + 32 * j;
        float qv = er[c];
        float x = xb[(size_t)c * 1024];
        float d = qv - x;
        ls = fmaf(d, d, ls);
        ob[(size_t)c * 1024] = qv;
    }
#pragma unroll
    for (int o = 16; o; o >>= 1) ls += __shfl_xor_sync(0xffffffffu, ls, o);
    if (lane == 0) {
        g_losspart[n] = ls;
        atomicAdd(&g_counts[idx], 1);
        out[IDX_OFF + n] = (float)idx;
    }
}

// ---------------- final scalars ----------------
__global__ void finalize_k(float* __restrict__ out) {
    __shared__ float sred[1024];
    int tid = threadIdx.x;
    float s = 0.f;
    for (int i = 0; i < 16; i++) s += g_losspart[tid + 1024 * i];
    sred[tid] = s; __syncthreads();
    for (int o = 512; o; o >>= 1) { if (tid < o) sred[tid] += sred[tid + o]; __syncthreads(); }
    if (tid == 0) out[LOSS_OFF] = 0.25f * (sred[0] * (1.0f / 4194304.0f));
    __syncthreads();
    float e = 0.f;
    for (int i = 0; i < 8; i++) {
        float p = (float)g_counts[tid + 1024 * i] * (1.0f / 16384.0f);
        e += p * logf(p + 1e-10f);
    }
    sred[tid] = e; __syncthreads();
    for (int o = 512; o; o >>= 1) { if (tid < o) sred[tid] += sred[tid + o]; __syncthreads(); }
    if (tid == 0) out[PERP_OFF] = expf(-sred[0]);
}

// ---------------- launcher ----------------
extern "C" void kernel_launch(void* const* d_in, const int* in_sizes, int n_in,
                              void* d_out, int out_size) {
    (void)in_sizes; (void)n_in; (void)out_size;
    const float* in  = (const float*)d_in[0];
    const float* emb = (const float*)d_in[1];
    float* out = (float*)d_out;

    const int dyn = 4 * BUFB;            // 135168 bytes
    cudaFuncSetAttribute(vq_mma, cudaFuncAttributeMaxDynamicSharedMemorySize, dyn);

    prep_w<<<KEMB / 8, 256>>>(emb);
    prep_x<<<NTOK / 8, 256>>>(in);
    zero_counts<<<32, 256>>>();
    vq_mma<<<NTOK / 128, 256, dyn>>>(out);
    refine_k<<<NTOK / 8, 256>>>();
    scale_soft<<<65536, 256>>>(out);
    quantize_k<<<NTOK / 8, 256>>>(in, emb, out);
    finalize_k<<<1, 1024>>>(out);
}